// round 5
// baseline (speedup 1.0000x reference)
#include <cuda_runtime.h>
#include <math.h>

// SmoothLDDTLoss — B=2, N=4096.
//
// Simplification: reference's c_lm = (dGT<30) | nuc | ((dGT<15) | ~nuc) contains
// (nuc | ~nuc) == True, so c_lm == ~eye(N): every off-diagonal pair counts;
// is_dna/is_rna are dead inputs.
//   loss = 1 - [ sum_{l!=m} 0.25*(sig(.5-d)+sig(1-d)+sig(2-d)+sig(4-d)) ] / (B*N*(N-1))
//   d = | ||xGT_l-xGT_m||^2 - ||x_l-x_m||^2 |
// eps symmetric: compute strict upper triangle, double it.
//
// Sigmoid-sum as one rational in e = exp(d):
//   S(e) = (s1 e^3 + 2 s2 e^2 + 3 s3 e + 4 s4) / (e^4 + s1 e^3 + s2 e^2 + s3 e + s4)
// s_k = elementary symmetric polys of {e^0.5, e^1, e^2, e^4}. 1 EX2 + 1 RCP per pair.
// |h| clamped (in log2 units) so e^4 stays finite in fp32 (error < 1e-7).
//
// Mainloop in packed f32x2 (1 row x 2 columns per thread). Reduction fused via
// last-block-done ticket; final sum over block partials is in a FIXED order ->
// deterministic. Single kernel launch total.

#define TILE 128
#define NTHREADS 256
#define MAX_BLOCKS 4096

__device__ float g_partials[MAX_BLOCKS];
__device__ unsigned int g_ticket;   // zero-init; reset by the elected last block

typedef unsigned long long u64;

__device__ __forceinline__ u64 pk2(float lo, float hi) {
    u64 r; asm("mov.b64 %0, {%1, %2};" : "=l"(r) : "f"(lo), "f"(hi)); return r;
}
__device__ __forceinline__ void upk2(u64 v, float& lo, float& hi) {
    asm("mov.b64 {%0, %1}, %2;" : "=f"(lo), "=f"(hi) : "l"(v));
}
__device__ __forceinline__ u64 f2add(u64 a, u64 b) {
    u64 r; asm("add.rn.f32x2 %0, %1, %2;" : "=l"(r) : "l"(a), "l"(b)); return r;
}
__device__ __forceinline__ u64 f2mul(u64 a, u64 b) {
    u64 r; asm("mul.rn.f32x2 %0, %1, %2;" : "=l"(r) : "l"(a), "l"(b)); return r;
}
__device__ __forceinline__ u64 f2fma(u64 a, u64 b, u64 c) {
    u64 r; asm("fma.rn.f32x2 %0, %1, %2, %3;" : "=l"(r) : "l"(a), "l"(b), "l"(c)); return r;
}
__device__ __forceinline__ float ex2a(float x) {
    float r; asm("ex2.approx.f32 %0, %1;" : "=f"(r) : "f"(x)); return r;
}
__device__ __forceinline__ float rcpa(float x) {
    float r; asm("rcp.approx.f32 %0, %1;" : "=f"(r) : "f"(x)); return r;
}

__global__ __launch_bounds__(NTHREADS) void lddt_tile_kernel(
    const float* __restrict__ x,   // [B, N, 3]
    const float* __restrict__ g,   // [B, N, 3]
    float* __restrict__ out,
    int N, int tilesPerBatch, int T, int grid, double invCount)
{
    // Column tile: 64 column-pairs x 6 attrs, pre-negated, packed as f32x2.
    __shared__ u64 scolp[64][6];
    __shared__ float warpSums[NTHREADS / 32];
    __shared__ bool isLast;

    const int id = blockIdx.x;
    const int b = id / tilesPerBatch;
    int rem = id % tilesPerBatch;
    // Closed-form triangular decode (ti <= tj): rem indexes rows of lengths T, T-1, ...
    int ti;
    {
        float fr = (float)rem;
        float tf = (float)T;
        ti = (int)floorf(tf + 0.5f - sqrtf((tf + 0.5f) * (tf + 0.5f) - 2.0f * fr));
        while (ti > 0 && rem < ti * T - (ti * (ti - 1)) / 2) ti--;
        while (rem >= (ti + 1) * T - ((ti + 1) * ti) / 2) ti++;
    }
    const int rowOff = ti * T - (ti * (ti - 1)) / 2;
    const int tj = ti + (rem - rowOff);

    const int t = threadIdx.x;
    const long rowBase = (long)(b * N + ti * TILE) * 3;
    const long colBase = (long)(b * N + tj * TILE) * 3;

    // Stage negated, packed column coords.
    for (int p = t; p < 64; p += NTHREADS) {
        const float* c0x = x + colBase + (2 * p) * 3;
        const float* c1x = x + colBase + (2 * p + 1) * 3;
        const float* c0g = g + colBase + (2 * p) * 3;
        const float* c1g = g + colBase + (2 * p + 1) * 3;
        scolp[p][0] = pk2(-c0x[0], -c1x[0]);
        scolp[p][1] = pk2(-c0x[1], -c1x[1]);
        scolp[p][2] = pk2(-c0x[2], -c1x[2]);
        scolp[p][3] = pk2(-c0g[0], -c1g[0]);
        scolp[p][4] = pk2(-c0g[1], -c1g[1]);
        scolp[p][5] = pk2(-c0g[2], -c1g[2]);
    }
    __syncthreads();

    // Thread layout: row r = t & 127 (register, broadcast-packed);
    // column-pairs p = (t>>7) + 2k, k = 0..31 — warp-uniform smem broadcast.
    const int r = t & 127;
    const int q = t >> 7;

    const float* rx = x + rowBase + r * 3;
    const float* rg = g + rowBase + r * 3;
    const u64 AX = pk2(rx[0], rx[0]);
    const u64 AY = pk2(rx[1], rx[1]);
    const u64 AZ = pk2(rx[2], rx[2]);
    const u64 GX = pk2(rg[0], rg[0]);
    const u64 GY = pk2(rg[1], rg[1]);
    const u64 GZ = pk2(rg[2], rg[2]);

    const float S1 = 66.35420923f, S2 = 678.6088038f, S3 = 2039.582176f, S4 = 1808.042414f;
    const float P3 = 66.35420923f, P2 = 1357.217608f, P1 = 6118.746527f, P0 = 7232.169658f;
    const u64 S1v = pk2(S1, S1), S2v = pk2(S2, S2), S3v = pk2(S3, S3), S4v = pk2(S4, S4);
    const u64 P3v = pk2(P3, P3), P2v = pk2(P2, P2), P1v = pk2(P1, P1), P0v = pk2(P0, P0);
    const u64 NEG1 = pk2(-1.0f, -1.0f);
    const u64 L2Ev = pk2(1.44269504f, 1.44269504f);
    const u64 ABSMASK = 0x7FFFFFFF7FFFFFFFULL;
    const float CLAMP = 30.3f;   // 21 * log2(e): keeps e^4 finite in fp32

    u64 accv = pk2(0.0f, 0.0f);
    float accs = 0.0f;                 // scalar acc for masked diagonal path

    if (ti != tj) {
        // Off-diagonal tile: all pairs strict-upper. Unmasked vector path.
#pragma unroll 4
        for (int k = 0; k < 32; k++) {
            const int p = q + 2 * k;
            const u64 cbx = scolp[p][0], cby = scolp[p][1], cbz = scolp[p][2];
            const u64 chx = scolp[p][3], chy = scolp[p][4], chz = scolp[p][5];

            u64 dxx = f2add(AX, cbx), dxy = f2add(AY, cby), dxz = f2add(AZ, cbz);
            u64 dgx = f2add(GX, chx), dgy = f2add(GY, chy), dgz = f2add(GZ, chz);
            u64 dx2 = f2fma(dxz, dxz, f2fma(dxy, dxy, f2mul(dxx, dxx)));
            u64 dg2 = f2fma(dgz, dgz, f2fma(dgy, dgy, f2mul(dgx, dgx)));
            u64 h = f2fma(dx2, NEG1, dg2);          // dg2 - dx2 per lane
            u64 hl = f2mul(h & ABSMASK, L2Ev);      // |h| * log2(e), packed

            float h0, h1; upk2(hl, h0, h1);
            float e0 = ex2a(fminf(h0, CLAMP));
            float e1 = ex2a(fminf(h1, CLAMP));
            u64 e = pk2(e0, e1);

            u64 P = f2fma(f2fma(f2fma(P3v, e, P2v), e, P1v), e, P0v);
            u64 Q = f2fma(f2fma(f2fma(f2add(e, S1v), e, S2v), e, S3v), e, S4v);
            float q0, q1; upk2(Q, q0, q1);
            u64 R = pk2(rcpa(q0), rcpa(q1));
            accv = f2fma(P, R, accv);
        }
    } else {
        // Diagonal tile: keep only strict-upper (r < m) contributions.
#pragma unroll 4
        for (int k = 0; k < 32; k++) {
            const int p = q + 2 * k;
            const int m0 = 2 * p, m1 = 2 * p + 1;
            const u64 cbx = scolp[p][0], cby = scolp[p][1], cbz = scolp[p][2];
            const u64 chx = scolp[p][3], chy = scolp[p][4], chz = scolp[p][5];

            u64 dxx = f2add(AX, cbx), dxy = f2add(AY, cby), dxz = f2add(AZ, cbz);
            u64 dgx = f2add(GX, chx), dgy = f2add(GY, chy), dgz = f2add(GZ, chz);
            u64 dx2 = f2fma(dxz, dxz, f2fma(dxy, dxy, f2mul(dxx, dxx)));
            u64 dg2 = f2fma(dgz, dgz, f2fma(dgy, dgy, f2mul(dgx, dgx)));
            u64 h = f2fma(dx2, NEG1, dg2);
            u64 hl = f2mul(h & ABSMASK, L2Ev);

            float h0, h1; upk2(hl, h0, h1);
            float e0 = ex2a(fminf(h0, CLAMP));
            float e1 = ex2a(fminf(h1, CLAMP));
            u64 e = pk2(e0, e1);

            u64 P = f2fma(f2fma(f2fma(P3v, e, P2v), e, P1v), e, P0v);
            u64 Q = f2fma(f2fma(f2fma(f2add(e, S1v), e, S2v), e, S3v), e, S4v);
            float q0, q1; upk2(Q, q0, q1);
            u64 s = f2mul(P, pk2(rcpa(q0), rcpa(q1)));
            float s0, s1; upk2(s, s0, s1);
            accs += (r < m0) ? s0 : 0.0f;
            accs += (r < m1) ? s1 : 0.0f;
        }
    }

    float a0, a1; upk2(accv, a0, a1);
    float acc = a0 + a1 + accs;

#pragma unroll
    for (int off = 16; off > 0; off >>= 1)
        acc += __shfl_down_sync(0xFFFFFFFFu, acc, off);
    if ((t & 31) == 0) warpSums[t >> 5] = acc;
    __syncthreads();
    if (t == 0) {
        float blockSum = 0.0f;
#pragma unroll
        for (int w = 0; w < NTHREADS / 32; w++) blockSum += warpSums[w];
        g_partials[blockIdx.x] = blockSum;     // deterministic partial
        __threadfence();                       // release: partial visible before ticket
        unsigned int ticket = atomicAdd(&g_ticket, 1u);
        isLast = (ticket == (unsigned int)(grid - 1));
    }
    __syncthreads();

    // Elected last block performs the final reduction in a FIXED order.
    if (isLast) {
        __shared__ double sd[NTHREADS];
        if (t == 0) g_ticket = 0;              // reset for next graph replay
        __threadfence();                       // acquire side for g_partials reads
        double s = 0.0;
        for (int i = t; i < grid; i += NTHREADS)
            s += (double)__ldcg(&g_partials[i]);
        sd[t] = s;
        __syncthreads();
#pragma unroll
        for (int off = NTHREADS / 2; off > 0; off >>= 1) {
            if (t < off) sd[t] += sd[t + off];
            __syncthreads();
        }
        if (t == 0) {
            // sum over l!=m = 2 * upper-triangle; eps carries the 0.25 factor.
            double lddt = 0.5 * sd[0] * invCount;   // 2 * 0.25 = 0.5
            out[0] = (float)(1.0 - lddt);
        }
    }
}

extern "C" void kernel_launch(void* const* d_in, const int* in_sizes, int n_in,
                              void* d_out, int out_size)
{
    const float* x = (const float*)d_in[0];   // x_l   [B,N,3] f32
    const float* g = (const float*)d_in[1];   // xGT_l [B,N,3] f32
    // d_in[2]/d_in[3] (is_dna/is_rna) provably unused: c_lm == ~eye.

    const int B = 2;
    const int N = in_sizes[0] / (3 * B);        // 4096
    const int T = N / TILE;                     // 32
    const int tilesPerBatch = T * (T + 1) / 2;  // 528
    const int grid = B * tilesPerBatch;         // 1056

    float* out = (float*)d_out;
    double invCount = 1.0 / ((double)B * (double)N * (double)(N - 1));

    lddt_tile_kernel<<<grid, NTHREADS>>>(x, g, out, N, tilesPerBatch, T, grid, invCount);
}

// round 9
// speedup vs baseline: 1.0376x; 1.0376x over previous
#include <cuda_runtime.h>
#include <math.h>

// SmoothLDDTLoss — B=2, N=4096.
//
// Simplification: reference's c_lm = (dGT<30) | nuc | ((dGT<15) | ~nuc) contains
// (nuc | ~nuc) == True, so c_lm == ~eye(N): every off-diagonal pair counts;
// is_dna/is_rna are dead inputs.
//   loss = 1 - [ sum_{l!=m} 0.25*(sig(.5-d)+sig(1-d)+sig(2-d)+sig(4-d)) ] / (B*N*(N-1))
//   d = | ||xGT_l-xGT_m||^2 - ||x_l-x_m||^2 |
// eps symmetric: strict upper triangle only, doubled.
//
// With u = exp(-d) in (0,1]:  Q(u) = prod_i (1 + K_i u) = 1 + s1 u + ... + s4 u^4
//   sum_i sig(c_i - d) = u * Q'(u) / Q(u)
// (K_i = e^{c_i}; s_k elementary symmetric polys). No overflow possible; u
// underflow -> 0 gives the exact limit S -> 0. 1 EX2 + 1 RCP per pair.
//
// Work unit: 128 rows x 64 cols half-tile -> 2112 blocks x 128 threads,
// 16 blocks/SM (single wave, ~5% skew). f32x2-packed mainloop (1 row x 2 cols
// per thread). Deterministic reduction: fixed-point s64 atomicAdd (associative
// integer adds -> order-independent result).

#define NTHREADS 128
#define TILE_R 128
#define TILE_C 64
#define SCALE 1048576.0   // 2^20 fixed-point

__device__ unsigned long long g_isum;   // zero-init; reset by elected last block
__device__ unsigned int g_count;

typedef unsigned long long u64;

__device__ __forceinline__ u64 pk2(float lo, float hi) {
    u64 r; asm("mov.b64 %0, {%1, %2};" : "=l"(r) : "f"(lo), "f"(hi)); return r;
}
__device__ __forceinline__ void upk2(u64 v, float& lo, float& hi) {
    asm("mov.b64 {%0, %1}, %2;" : "=f"(lo), "=f"(hi) : "l"(v));
}
__device__ __forceinline__ u64 f2add(u64 a, u64 b) {
    u64 r; asm("add.rn.f32x2 %0, %1, %2;" : "=l"(r) : "l"(a), "l"(b)); return r;
}
__device__ __forceinline__ u64 f2mul(u64 a, u64 b) {
    u64 r; asm("mul.rn.f32x2 %0, %1, %2;" : "=l"(r) : "l"(a), "l"(b)); return r;
}
__device__ __forceinline__ u64 f2fma(u64 a, u64 b, u64 c) {
    u64 r; asm("fma.rn.f32x2 %0, %1, %2, %3;" : "=l"(r) : "l"(a), "l"(b), "l"(c)); return r;
}
__device__ __forceinline__ float ex2a(float x) {
    float r; asm("ex2.approx.f32 %0, %1;" : "=f"(r) : "f"(x)); return r;
}
__device__ __forceinline__ float rcpa(float x) {
    float r; asm("rcp.approx.f32 %0, %1;" : "=f"(r) : "f"(x)); return r;
}

__global__ __launch_bounds__(NTHREADS, 16) void lddt_kernel(
    const float* __restrict__ x,   // [B, N, 3]
    const float* __restrict__ g,   // [B, N, 3]
    float* __restrict__ out,
    int N, int tilesPerBatch, int T, int nUnits, double invCount)
{
    // 32 column-pairs x 6 attrs (pre-negated, f32x2-packed), 48B record ->
    // three 16B-aligned LDS.128 per pair.
    __shared__ __align__(16) u64 scolp[TILE_C / 2][6];
    __shared__ float warpSums[NTHREADS / 32];

    const int uid = blockIdx.x;
    const int tile = uid >> 1;          // which 128x128 tile
    const int half = uid & 1;           // which 64-col half
    const int b = tile / tilesPerBatch;
    int rem = tile % tilesPerBatch;
    // Closed-form triangular decode (ti <= tj).
    int ti;
    {
        float tf = (float)T;
        ti = (int)floorf(tf + 0.5f - sqrtf((tf + 0.5f) * (tf + 0.5f) - 2.0f * (float)rem));
        while (ti > 0 && rem < ti * T - (ti * (ti - 1)) / 2) ti--;
        while (rem >= (ti + 1) * T - ((ti + 1) * ti) / 2) ti++;
    }
    const int rowOff = ti * T - (ti * (ti - 1)) / 2;
    const int tj = ti + (rem - rowOff);

    const int t = threadIdx.x;
    const long rowBase = (long)(b * N + ti * TILE_R) * 3;
    const long colBase = (long)(b * N + tj * TILE_R + half * TILE_C) * 3;

    // Stage negated, packed column coords (threads 0..31, one pair each).
    if (t < TILE_C / 2) {
        const int p = t;
        const float* c0x = x + colBase + (2 * p) * 3;
        const float* c1x = x + colBase + (2 * p + 1) * 3;
        const float* c0g = g + colBase + (2 * p) * 3;
        const float* c1g = g + colBase + (2 * p + 1) * 3;
        scolp[p][0] = pk2(-c0x[0], -c1x[0]);
        scolp[p][1] = pk2(-c0x[1], -c1x[1]);
        scolp[p][2] = pk2(-c0x[2], -c1x[2]);
        scolp[p][3] = pk2(-c0g[0], -c1g[0]);
        scolp[p][4] = pk2(-c0g[1], -c1g[1]);
        scolp[p][5] = pk2(-c0g[2], -c1g[2]);
    }

    // Row r = t (register-resident, broadcast-packed).
    const int r = t;
    const float* rx = x + rowBase + r * 3;
    const float* rg = g + rowBase + r * 3;
    const float rx0 = rx[0], rx1 = rx[1], rx2 = rx[2];
    const float rg0 = rg[0], rg1 = rg[1], rg2 = rg[2];
    const u64 AX = pk2(rx0, rx0), AY = pk2(rx1, rx1), AZ = pk2(rx2, rx2);
    const u64 GX = pk2(rg0, rg0), GY = pk2(rg1, rg1), GZ = pk2(rg2, rg2);
    __syncthreads();

    // Q(u) = 1 + s1 u + s2 u^2 + s3 u^3 + s4 u^4 ; numerator u*Q'(u).
    const float S1 = 66.35420923f, S2 = 678.6088038f, S3 = 2039.582176f, S4 = 1808.042414f;
    const u64 S1v = pk2(S1, S1), S2v = pk2(S2, S2), S3v = pk2(S3, S3), S4v = pk2(S4, S4);
    const u64 C1v = S1v;                              // s1
    const u64 C2v = pk2(2 * S2, 2 * S2);              // 2 s2
    const u64 C3v = pk2(3 * S3, 3 * S3);              // 3 s3
    const u64 C4v = pk2(4 * S4, 4 * S4);              // 4 s4
    const u64 ONEv = pk2(1.0f, 1.0f);
    const u64 NEG1 = pk2(-1.0f, -1.0f);
    const float NL2E = -1.44269504f;                  // -log2(e)

    u64 accv = pk2(0.0f, 0.0f);
    float accs = 0.0f;

    const bool diag = (ti == tj);
    const int mBase = half * TILE_C;                  // col offset within 128-tile

#pragma unroll 8
    for (int p = 0; p < TILE_C / 2; p++) {
        const ulonglong2* sp = (const ulonglong2*)&scolp[p][0];
        const ulonglong2 v0 = sp[0];   // {-bx, -by}
        const ulonglong2 v1 = sp[1];   // {-bz, -hx}
        const ulonglong2 v2 = sp[2];   // {-hy, -hz}

        u64 dxx = f2add(AX, v0.x), dxy = f2add(AY, v0.y), dxz = f2add(AZ, v1.x);
        u64 dgx = f2add(GX, v1.y), dgy = f2add(GY, v2.x), dgz = f2add(GZ, v2.y);
        u64 dx2 = f2fma(dxz, dxz, f2fma(dxy, dxy, f2mul(dxx, dxx)));
        u64 dg2 = f2fma(dgz, dgz, f2fma(dgy, dgy, f2mul(dgx, dgx)));
        u64 h = f2fma(dx2, NEG1, dg2);                // dg2 - dx2 per lane

        float h0, h1; upk2(h, h0, h1);
        float u0 = ex2a(fabsf(h0) * NL2E);            // exp(-|h|); underflow->0 exact
        float u1 = ex2a(fabsf(h1) * NL2E);
        u64 u = pk2(u0, u1);

        u64 Qp = f2fma(f2fma(f2fma(C4v, u, C3v), u, C2v), u, C1v);
        u64 Q  = f2fma(f2fma(f2fma(f2fma(S4v, u, S3v), u, S2v), u, S1v), u, ONEv);
        u64 P  = f2mul(u, Qp);
        float q0, q1; upk2(Q, q0, q1);
        u64 R = pk2(rcpa(q0), rcpa(q1));

        if (!diag) {
            accv = f2fma(P, R, accv);
        } else {
            u64 s = f2mul(P, R);
            float s0, s1; upk2(s, s0, s1);
            accs += (r < mBase + 2 * p) ? s0 : 0.0f;      // strict upper only
            accs += (r < mBase + 2 * p + 1) ? s1 : 0.0f;
        }
    }

    float a0, a1; upk2(accv, a0, a1);
    float acc = a0 + a1 + accs;

#pragma unroll
    for (int off = 16; off > 0; off >>= 1)
        acc += __shfl_down_sync(0xFFFFFFFFu, acc, off);
    if ((t & 31) == 0) warpSums[t >> 5] = acc;
    __syncthreads();

    if (t == 0) {
        float blockSum = warpSums[0] + warpSums[1] + warpSums[2] + warpSums[3];
        // Fixed-point accumulate: integer adds are associative -> deterministic
        // regardless of block arrival order. Quantization bias ~2112 * 5e-7
        // absolute on a ~5e7 sum -> ~1e-11 relative.
        long long qv = __double2ll_rn((double)blockSum * SCALE);
        atomicAdd(&g_isum, (unsigned long long)qv);
        __threadfence();
        unsigned int old = atomicAdd(&g_count, 1u);
        if (old == (unsigned int)(nUnits - 1)) {
            // Every block's g_isum add is ordered before its count add by the
            // fence, so the total is complete and visible here.
            __threadfence();
            unsigned long long tot = *((volatile unsigned long long*)&g_isum);
            double s = (double)(long long)tot * (1.0 / SCALE);
            // sum over l!=m = 2 * upper-triangle; eps carries the 0.25 factor.
            out[0] = (float)(1.0 - 0.5 * s * invCount);
            g_isum = 0ULL;          // reset for next graph replay
            g_count = 0u;
        }
    }
}

extern "C" void kernel_launch(void* const* d_in, const int* in_sizes, int n_in,
                              void* d_out, int out_size)
{
    const float* x = (const float*)d_in[0];   // x_l   [B,N,3] f32
    const float* g = (const float*)d_in[1];   // xGT_l [B,N,3] f32
    // d_in[2]/d_in[3] (is_dna/is_rna) provably unused: c_lm == ~eye.

    const int B = 2;
    const int N = in_sizes[0] / (3 * B);        // 4096
    const int T = N / TILE_R;                   // 32
    const int tilesPerBatch = T * (T + 1) / 2;  // 528
    const int nUnits = B * tilesPerBatch * 2;   // 2112 half-tiles

    float* out = (float*)d_out;
    double invCount = 1.0 / ((double)B * (double)N * (double)(N - 1));

    lddt_kernel<<<nUnits, NTHREADS>>>(x, g, out, N, tilesPerBatch, T, nUnits, invCount);
}

// round 10
// speedup vs baseline: 1.0906x; 1.0510x over previous
#include <cuda_runtime.h>
#include <math.h>

// SmoothLDDTLoss — B=2, N=4096.
//
// Simplification: reference's c_lm = (dGT<30) | nuc | ((dGT<15) | ~nuc) contains
// (nuc | ~nuc) == True, so c_lm == ~eye(N): every off-diagonal pair counts;
// is_dna/is_rna are dead inputs.
//   loss = 1 - [ sum_{l!=m} 0.25*(sig(.5-d)+sig(1-d)+sig(2-d)+sig(4-d)) ] / (B*N*(N-1))
//   d = | ||xGT_l-xGT_m||^2 - ||x_l-x_m||^2 |
//
// With u = exp(-d) in (0,1]:  Q(u) = prod_i (1 + K_i u) = 1 + s1 u + ... + s4 u^4
//   sum_i sig(c_i - d) = u * Q'(u) / Q(u)        (1 EX2 + 1 RCP per pair)
// u underflow -> 0 gives the exact limit S -> 0; no overflow possible.
//
// Triangular tiling with analytic diagonal correction (branch-free mainloop):
//   sum_{l!=m} S = 2*Sum_offdiag_tiles + Sum_diag_tiles - B*N*S(1),
// where S(1) = sig(.5)+sig(1)+sig(2)+sig(4) = 3.216328778 (d=0 diagonal value).
// Every block computes its full 128x128 tile unmasked; off-diag tiles weighted
// x2, diagonal tiles x1.
//
// Mainloop: f32x2-packed, 1 row x 2 cols per thread, 64 iterations.
// Deterministic reduction: fixed-point s64 atomicAdd (integer adds associative).

#define NTHREADS 128
#define TILE 128
#define SCALE 1048576.0   // 2^20 fixed-point

__device__ unsigned long long g_isum;   // zero-init; reset by elected last block
__device__ unsigned int g_count;

typedef unsigned long long u64;

__device__ __forceinline__ u64 pk2(float lo, float hi) {
    u64 r; asm("mov.b64 %0, {%1, %2};" : "=l"(r) : "f"(lo), "f"(hi)); return r;
}
__device__ __forceinline__ void upk2(u64 v, float& lo, float& hi) {
    asm("mov.b64 {%0, %1}, %2;" : "=f"(lo), "=f"(hi) : "l"(v));
}
__device__ __forceinline__ u64 f2add(u64 a, u64 b) {
    u64 r; asm("add.rn.f32x2 %0, %1, %2;" : "=l"(r) : "l"(a), "l"(b)); return r;
}
__device__ __forceinline__ u64 f2mul(u64 a, u64 b) {
    u64 r; asm("mul.rn.f32x2 %0, %1, %2;" : "=l"(r) : "l"(a), "l"(b)); return r;
}
__device__ __forceinline__ u64 f2fma(u64 a, u64 b, u64 c) {
    u64 r; asm("fma.rn.f32x2 %0, %1, %2, %3;" : "=l"(r) : "l"(a), "l"(b), "l"(c)); return r;
}
__device__ __forceinline__ float ex2a(float x) {
    float r; asm("ex2.approx.f32 %0, %1;" : "=f"(r) : "f"(x)); return r;
}
__device__ __forceinline__ float rcpa(float x) {
    float r; asm("rcp.approx.f32 %0, %1;" : "=f"(r) : "f"(x)); return r;
}

__global__ __launch_bounds__(NTHREADS, 16) void lddt_kernel(
    const float* __restrict__ x,   // [B, N, 3]
    const float* __restrict__ g,   // [B, N, 3]
    float* __restrict__ out,
    int N, int tilesPerBatch, int T, int nUnits,
    double invCount, double diagTerm)
{
    // 64 column-pairs x 6 attrs (pre-negated, f32x2-packed), 48B record ->
    // three 16B-aligned LDS.128 per pair.
    __shared__ __align__(16) u64 scolp[TILE / 2][6];
    __shared__ float warpSums[NTHREADS / 32];

    const int tile = blockIdx.x;
    const int b = tile / tilesPerBatch;
    int rem = tile % tilesPerBatch;
    // Closed-form triangular decode (ti <= tj).
    int ti;
    {
        float tf = (float)T;
        ti = (int)floorf(tf + 0.5f - sqrtf((tf + 0.5f) * (tf + 0.5f) - 2.0f * (float)rem));
        while (ti > 0 && rem < ti * T - (ti * (ti - 1)) / 2) ti--;
        while (rem >= (ti + 1) * T - ((ti + 1) * ti) / 2) ti++;
    }
    const int rowOff = ti * T - (ti * (ti - 1)) / 2;
    const int tj = ti + (rem - rowOff);

    const int t = threadIdx.x;
    const long rowBase = (long)(b * N + ti * TILE) * 3;
    const long colBase = (long)(b * N + tj * TILE) * 3;

    // Stage negated, packed column coords (threads 0..63, one pair each).
    if (t < TILE / 2) {
        const int p = t;
        const float* c0x = x + colBase + (2 * p) * 3;
        const float* c1x = x + colBase + (2 * p + 1) * 3;
        const float* c0g = g + colBase + (2 * p) * 3;
        const float* c1g = g + colBase + (2 * p + 1) * 3;
        scolp[p][0] = pk2(-c0x[0], -c1x[0]);
        scolp[p][1] = pk2(-c0x[1], -c1x[1]);
        scolp[p][2] = pk2(-c0x[2], -c1x[2]);
        scolp[p][3] = pk2(-c0g[0], -c1g[0]);
        scolp[p][4] = pk2(-c0g[1], -c1g[1]);
        scolp[p][5] = pk2(-c0g[2], -c1g[2]);
    }

    // Row r = t (register-resident, broadcast-packed).
    const int r = t;
    const float* rx = x + rowBase + r * 3;
    const float* rg = g + rowBase + r * 3;
    const float rx0 = rx[0], rx1 = rx[1], rx2 = rx[2];
    const float rg0 = rg[0], rg1 = rg[1], rg2 = rg[2];
    const u64 AX = pk2(rx0, rx0), AY = pk2(rx1, rx1), AZ = pk2(rx2, rx2);
    const u64 GX = pk2(rg0, rg0), GY = pk2(rg1, rg1), GZ = pk2(rg2, rg2);
    __syncthreads();

    // Q(u) = 1 + s1 u + s2 u^2 + s3 u^3 + s4 u^4 ; numerator u*Q'(u).
    const float S1 = 66.35420923f, S2 = 678.6088038f, S3 = 2039.582176f, S4 = 1808.042414f;
    const u64 S1v = pk2(S1, S1), S2v = pk2(S2, S2), S3v = pk2(S3, S3), S4v = pk2(S4, S4);
    const u64 C1v = S1v;                              // s1
    const u64 C2v = pk2(2 * S2, 2 * S2);              // 2 s2
    const u64 C3v = pk2(3 * S3, 3 * S3);              // 3 s3
    const u64 C4v = pk2(4 * S4, 4 * S4);              // 4 s4
    const u64 ONEv = pk2(1.0f, 1.0f);
    const u64 NEG1 = pk2(-1.0f, -1.0f);
    const float NL2E = -1.44269504f;                  // -log2(e)

    u64 accv = pk2(0.0f, 0.0f);

    // Branch-free, unmasked mainloop: identical for ALL tiles.
#pragma unroll 8
    for (int p = 0; p < TILE / 2; p++) {
        const ulonglong2* sp = (const ulonglong2*)&scolp[p][0];
        const ulonglong2 v0 = sp[0];   // {-bx, -by}
        const ulonglong2 v1 = sp[1];   // {-bz, -hx}
        const ulonglong2 v2 = sp[2];   // {-hy, -hz}

        u64 dxx = f2add(AX, v0.x), dxy = f2add(AY, v0.y), dxz = f2add(AZ, v1.x);
        u64 dgx = f2add(GX, v1.y), dgy = f2add(GY, v2.x), dgz = f2add(GZ, v2.y);
        u64 dx2 = f2fma(dxz, dxz, f2fma(dxy, dxy, f2mul(dxx, dxx)));
        u64 dg2 = f2fma(dgz, dgz, f2fma(dgy, dgy, f2mul(dgx, dgx)));
        u64 h = f2fma(dx2, NEG1, dg2);                // dg2 - dx2 per lane

        float h0, h1; upk2(h, h0, h1);
        float u0 = ex2a(fabsf(h0) * NL2E);            // exp(-|h|); underflow->0 exact
        float u1 = ex2a(fabsf(h1) * NL2E);
        u64 u = pk2(u0, u1);

        u64 Qp = f2fma(f2fma(f2fma(C4v, u, C3v), u, C2v), u, C1v);
        u64 Q  = f2fma(f2fma(f2fma(f2fma(S4v, u, S3v), u, S2v), u, S1v), u, ONEv);
        u64 P  = f2mul(u, Qp);
        float q0, q1; upk2(Q, q0, q1);
        u64 R = pk2(rcpa(q0), rcpa(q1));
        accv = f2fma(P, R, accv);
    }

    float a0, a1; upk2(accv, a0, a1);
    float acc = a0 + a1;

#pragma unroll
    for (int off = 16; off > 0; off >>= 1)
        acc += __shfl_down_sync(0xFFFFFFFFu, acc, off);
    if ((t & 31) == 0) warpSums[t >> 5] = acc;
    __syncthreads();

    if (t == 0) {
        float blockSum = warpSums[0] + warpSums[1] + warpSums[2] + warpSums[3];
        // Off-diagonal tiles count twice (symmetry); diagonal tiles once.
        double w = (ti == tj) ? 1.0 : 2.0;
        // Fixed-point accumulate: integer adds associative -> deterministic.
        long long qv = __double2ll_rn((double)blockSum * w * SCALE);
        atomicAdd(&g_isum, (unsigned long long)qv);
        __threadfence();
        unsigned int old = atomicAdd(&g_count, 1u);
        if (old == (unsigned int)(nUnits - 1)) {
            __threadfence();
            unsigned long long tot = *((volatile unsigned long long*)&g_isum);
            double s = (double)(long long)tot * (1.0 / SCALE);
            // sum_{l!=m} S = s - B*N*S(1); eps carries the 0.25 factor.
            out[0] = (float)(1.0 - 0.25 * (s - diagTerm) * invCount);
            g_isum = 0ULL;          // reset for next graph replay
            g_count = 0u;
        }
    }
}

extern "C" void kernel_launch(void* const* d_in, const int* in_sizes, int n_in,
                              void* d_out, int out_size)
{
    const float* x = (const float*)d_in[0];   // x_l   [B,N,3] f32
    const float* g = (const float*)d_in[1];   // xGT_l [B,N,3] f32
    // d_in[2]/d_in[3] (is_dna/is_rna) provably unused: c_lm == ~eye.

    const int B = 2;
    const int N = in_sizes[0] / (3 * B);        // 4096
    const int T = N / TILE;                     // 32
    const int tilesPerBatch = T * (T + 1) / 2;  // 528
    const int nUnits = B * tilesPerBatch;       // 1056 full tiles

    float* out = (float*)d_out;
    double invCount = 1.0 / ((double)B * (double)N * (double)(N - 1));
    // S(1) = sig(.5)+sig(1)+sig(2)+sig(4), the d=0 diagonal contribution.
    double diagTerm = (double)B * (double)N * 3.216328778234624;

    lddt_kernel<<<nUnits, NTHREADS>>>(x, g, out, N, tilesPerBatch, T, nUnits,
                                      invCount, diagTerm);
}

// round 12
// speedup vs baseline: 1.0920x; 1.0013x over previous
#include <cuda_runtime.h>
#include <math.h>

// SmoothLDDTLoss — B=2, N=4096.
//
// c_lm in the reference contains (nuc | ~nuc) == True -> c_lm == ~eye(N);
// is_dna/is_rna are dead inputs.
//   loss = 1 - [ sum_{l!=m} 0.25*(sig(.5-d)+sig(1-d)+sig(2-d)+sig(4-d)) ] / (B*N*(N-1))
//   d = | ||xGT_l-xGT_m||^2 - ||x_l-x_m||^2 |
//
// u = exp(-d) in (0,1]:  Q(u) = 1 + s1 u + s2 u^2 + s3 u^3 + s4 u^4,
//   sum_i sig(c_i - d) = u * Q'(u) / Q(u)     (1 EX2 + 1 RCP per pair)
//
// Triangular 128x128 tiles, unmasked + analytic diagonal correction:
//   sum_{l!=m} = 2*Sum_offdiag + Sum_diag - B*N*S(1),  S(1)=3.216328778.
//
// Mainloop: 2 rows x 2 packed cols per thread per iteration (32 iters) —
// column LDS + loop overhead amortized across two rows.
// Deterministic reduction: fixed-point s64 atomicAdd.

#define NTHREADS 128
#define TILE 128
#define SCALE 1048576.0   // 2^20 fixed-point

__device__ unsigned long long g_isum;   // zero-init; reset by elected last block
__device__ unsigned int g_count;

typedef unsigned long long u64;

__device__ __forceinline__ u64 pk2(float lo, float hi) {
    u64 r; asm("mov.b64 %0, {%1, %2};" : "=l"(r) : "f"(lo), "f"(hi)); return r;
}
__device__ __forceinline__ void upk2(u64 v, float& lo, float& hi) {
    asm("mov.b64 {%0, %1}, %2;" : "=f"(lo), "=f"(hi) : "l"(v));
}
__device__ __forceinline__ u64 f2add(u64 a, u64 b) {
    u64 r; asm("add.rn.f32x2 %0, %1, %2;" : "=l"(r) : "l"(a), "l"(b)); return r;
}
__device__ __forceinline__ u64 f2mul(u64 a, u64 b) {
    u64 r; asm("mul.rn.f32x2 %0, %1, %2;" : "=l"(r) : "l"(a), "l"(b)); return r;
}
__device__ __forceinline__ u64 f2fma(u64 a, u64 b, u64 c) {
    u64 r; asm("fma.rn.f32x2 %0, %1, %2, %3;" : "=l"(r) : "l"(a), "l"(b), "l"(c)); return r;
}
__device__ __forceinline__ float ex2a(float x) {
    float r; asm("ex2.approx.f32 %0, %1;" : "=f"(r) : "f"(x)); return r;
}
__device__ __forceinline__ float rcpa(float x) {
    float r; asm("rcp.approx.f32 %0, %1;" : "=f"(r) : "f"(x)); return r;
}

__global__ __launch_bounds__(NTHREADS) void lddt_kernel(
    const float* __restrict__ x,   // [B, N, 3]
    const float* __restrict__ g,   // [B, N, 3]
    float* __restrict__ out,
    int N, int tilesPerBatch, int T, int nUnits,
    double invCount, double diagTerm)
{
    // 64 column-pairs x 6 attrs (pre-negated, f32x2-packed), 48B record ->
    // three 16B-aligned LDS.128 per pair.
    __shared__ __align__(16) u64 scolp[TILE / 2][6];
    __shared__ float warpSums[NTHREADS / 32];

    const int tile = blockIdx.x;
    const int b = tile / tilesPerBatch;
    int rem = tile % tilesPerBatch;
    // Closed-form triangular decode (ti <= tj).
    int ti;
    {
        float tf = (float)T;
        ti = (int)floorf(tf + 0.5f - sqrtf((tf + 0.5f) * (tf + 0.5f) - 2.0f * (float)rem));
        while (ti > 0 && rem < ti * T - (ti * (ti - 1)) / 2) ti--;
        while (rem >= (ti + 1) * T - ((ti + 1) * ti) / 2) ti++;
    }
    const int rowOff = ti * T - (ti * (ti - 1)) / 2;
    const int tj = ti + (rem - rowOff);

    const int t = threadIdx.x;
    const long rowBase = (long)(b * N + ti * TILE) * 3;
    const long colBase = (long)(b * N + tj * TILE) * 3;

    // Stage negated, packed column coords (threads 0..63, one pair each).
    if (t < TILE / 2) {
        const int p = t;
        const float* c0x = x + colBase + (2 * p) * 3;
        const float* c1x = x + colBase + (2 * p + 1) * 3;
        const float* c0g = g + colBase + (2 * p) * 3;
        const float* c1g = g + colBase + (2 * p + 1) * 3;
        scolp[p][0] = pk2(-c0x[0], -c1x[0]);
        scolp[p][1] = pk2(-c0x[1], -c1x[1]);
        scolp[p][2] = pk2(-c0x[2], -c1x[2]);
        scolp[p][3] = pk2(-c0g[0], -c1g[0]);
        scolp[p][4] = pk2(-c0g[1], -c1g[1]);
        scolp[p][5] = pk2(-c0g[2], -c1g[2]);
    }

    // Thread t owns rows rA = t&63 and rB = rA+64; column-pairs p = (t>>6)+2k.
    const int rA = t & 63;
    const int rB = rA + 64;
    const int h = t >> 6;              // warp-uniform (warps 0,1 -> 0; 2,3 -> 1)

    const float* rxA = x + rowBase + rA * 3;
    const float* rgA = g + rowBase + rA * 3;
    const float* rxB = x + rowBase + rB * 3;
    const float* rgB = g + rowBase + rB * 3;
    const u64 AXa = pk2(rxA[0], rxA[0]), AYa = pk2(rxA[1], rxA[1]), AZa = pk2(rxA[2], rxA[2]);
    const u64 GXa = pk2(rgA[0], rgA[0]), GYa = pk2(rgA[1], rgA[1]), GZa = pk2(rgA[2], rgA[2]);
    const u64 AXb = pk2(rxB[0], rxB[0]), AYb = pk2(rxB[1], rxB[1]), AZb = pk2(rxB[2], rxB[2]);
    const u64 GXb = pk2(rgB[0], rgB[0]), GYb = pk2(rgB[1], rgB[1]), GZb = pk2(rgB[2], rgB[2]);
    __syncthreads();

    // Q(u) = 1 + s1 u + s2 u^2 + s3 u^3 + s4 u^4 ; numerator u*Q'(u).
    const float S1 = 66.35420923f, S2 = 678.6088038f, S3 = 2039.582176f, S4 = 1808.042414f;
    const u64 S1v = pk2(S1, S1), S2v = pk2(S2, S2), S3v = pk2(S3, S3), S4v = pk2(S4, S4);
    const u64 C1v = S1v;
    const u64 C2v = pk2(2 * S2, 2 * S2);
    const u64 C3v = pk2(3 * S3, 3 * S3);
    const u64 C4v = pk2(4 * S4, 4 * S4);
    const u64 ONEv = pk2(1.0f, 1.0f);
    const u64 NEG1 = pk2(-1.0f, -1.0f);
    const float NL2E = -1.44269504f;                  // -log2(e)

    u64 accA = pk2(0.0f, 0.0f);
    u64 accB = pk2(0.0f, 0.0f);

    // Branch-free, unmasked mainloop — identical for all tiles.
#pragma unroll 4
    for (int k = 0; k < 32; k++) {
        const int p = h + 2 * k;
        const ulonglong2* sp = (const ulonglong2*)&scolp[p][0];
        const ulonglong2 v0 = sp[0];   // {-bx, -by}
        const ulonglong2 v1 = sp[1];   // {-bz, -hx}
        const ulonglong2 v2 = sp[2];   // {-hy, -hz}

        // Row A
        {
            u64 dxx = f2add(AXa, v0.x), dxy = f2add(AYa, v0.y), dxz = f2add(AZa, v1.x);
            u64 dgx = f2add(GXa, v1.y), dgy = f2add(GYa, v2.x), dgz = f2add(GZa, v2.y);
            u64 dx2 = f2fma(dxz, dxz, f2fma(dxy, dxy, f2mul(dxx, dxx)));
            u64 dg2 = f2fma(dgz, dgz, f2fma(dgy, dgy, f2mul(dgx, dgx)));
            u64 hv = f2fma(dx2, NEG1, dg2);
            float h0, h1; upk2(hv, h0, h1);
            float u0 = ex2a(fabsf(h0) * NL2E);
            float u1 = ex2a(fabsf(h1) * NL2E);
            u64 u = pk2(u0, u1);
            u64 Qp = f2fma(f2fma(f2fma(C4v, u, C3v), u, C2v), u, C1v);
            u64 Q  = f2fma(f2fma(f2fma(f2fma(S4v, u, S3v), u, S2v), u, S1v), u, ONEv);
            u64 P  = f2mul(u, Qp);
            float q0, q1; upk2(Q, q0, q1);
            u64 R = pk2(rcpa(q0), rcpa(q1));
            accA = f2fma(P, R, accA);
        }
        // Row B
        {
            u64 dxx = f2add(AXb, v0.x), dxy = f2add(AYb, v0.y), dxz = f2add(AZb, v1.x);
            u64 dgx = f2add(GXb, v1.y), dgy = f2add(GYb, v2.x), dgz = f2add(GZb, v2.y);
            u64 dx2 = f2fma(dxz, dxz, f2fma(dxy, dxy, f2mul(dxx, dxx)));
            u64 dg2 = f2fma(dgz, dgz, f2fma(dgy, dgy, f2mul(dgx, dgx)));
            u64 hv = f2fma(dx2, NEG1, dg2);
            float h0, h1; upk2(hv, h0, h1);
            float u0 = ex2a(fabsf(h0) * NL2E);
            float u1 = ex2a(fabsf(h1) * NL2E);
            u64 u = pk2(u0, u1);
            u64 Qp = f2fma(f2fma(f2fma(C4v, u, C3v), u, C2v), u, C1v);
            u64 Q  = f2fma(f2fma(f2fma(f2fma(S4v, u, S3v), u, S2v), u, S1v), u, ONEv);
            u64 P  = f2mul(u, Qp);
            float q0, q1; upk2(Q, q0, q1);
            u64 R = pk2(rcpa(q0), rcpa(q1));
            accB = f2fma(P, R, accB);
        }
    }

    u64 accv = f2add(accA, accB);
    float a0, a1; upk2(accv, a0, a1);
    float acc = a0 + a1;

#pragma unroll
    for (int off = 16; off > 0; off >>= 1)
        acc += __shfl_down_sync(0xFFFFFFFFu, acc, off);
    if ((t & 31) == 0) warpSums[t >> 5] = acc;
    __syncthreads();

    if (t == 0) {
        float blockSum = warpSums[0] + warpSums[1] + warpSums[2] + warpSums[3];
        // Off-diagonal tiles count twice (symmetry); diagonal tiles once.
        double w = (ti == tj) ? 1.0 : 2.0;
        long long qv = __double2ll_rn((double)blockSum * w * SCALE);
        atomicAdd(&g_isum, (unsigned long long)qv);
        __threadfence();
        unsigned int old = atomicAdd(&g_count, 1u);
        if (old == (unsigned int)(nUnits - 1)) {
            __threadfence();
            unsigned long long tot = *((volatile unsigned long long*)&g_isum);
            double s = (double)(long long)tot * (1.0 / SCALE);
            // sum_{l!=m} S = s - B*N*S(1); eps carries the 0.25 factor.
            out[0] = (float)(1.0 - 0.25 * (s - diagTerm) * invCount);
            g_isum = 0ULL;          // reset for next graph replay
            g_count = 0u;
        }
    }
}

extern "C" void kernel_launch(void* const* d_in, const int* in_sizes, int n_in,
                              void* d_out, int out_size)
{
    const float* x = (const float*)d_in[0];   // x_l   [B,N,3] f32
    const float* g = (const float*)d_in[1];   // xGT_l [B,N,3] f32
    // d_in[2]/d_in[3] (is_dna/is_rna) provably unused: c_lm == ~eye.

    const int B = 2;
    const int N = in_sizes[0] / (3 * B);        // 4096
    const int T = N / TILE;                     // 32
    const int tilesPerBatch = T * (T + 1) / 2;  // 528
    const int nUnits = B * tilesPerBatch;       // 1056 full tiles

    float* out = (float*)d_out;
    double invCount = 1.0 / ((double)B * (double)N * (double)(N - 1));
    // S(1) = sig(.5)+sig(1)+sig(2)+sig(4), the d=0 diagonal contribution.
    double diagTerm = (double)B * (double)N * 3.216328778234624;

    lddt_kernel<<<nUnits, NTHREADS>>>(x, g, out, N, tilesPerBatch, T, nUnits,
                                      invCount, diagTerm);
}